// round 13
// baseline (speedup 1.0000x reference)
#include <cuda_runtime.h>
#include <cstdint>

// Problem constants: B=16, Q=2048, K=2048, D=512, fp32.
#define NB 16
#define NQ 2048
#define NK 2048
#define ND 512

// Scratch for whichever of (context, weights) is NOT part of d_out.
__device__ float g_scratch[(size_t)NB * NQ * NK];
__device__ __forceinline__ float* sel_or_scratch(float* p) { return p ? p : g_scratch; }

#define BM 128
#define BN 128
#define BKc 8
#define AP 132   // float2 row pad: 2*132 mod 32 = 8 -> frag LDS.64 conflict-free

__device__ __forceinline__ float f2tf(float v) {
    uint32_t r; asm("cvt.rna.tf32.f32 %0, %1;" : "=r"(r) : "f"(v));
    return __uint_as_float(r);
}
// v = hi + lo, both tf32-representable. 3-term product residual ~(2^-11)^2.
__device__ __forceinline__ float2 split2(float v) {
    float hi = f2tf(v);
    return make_float2(hi, f2tf(v - hi));
}

// D += A*B, tf32 m16n8k8, A row-major, B col-major.
__device__ __forceinline__ void mma_tf32(float c[4], const uint32_t a[4], const uint32_t b[2]) {
    asm("mma.sync.aligned.m16n8k8.row.col.f32.tf32.tf32.f32 "
        "{%0,%1,%2,%3}, {%4,%5,%6,%7}, {%8,%9}, {%0,%1,%2,%3};"
        : "+f"(c[0]), "+f"(c[1]), "+f"(c[2]), "+f"(c[3])
        : "r"(a[0]), "r"(a[1]), "r"(a[2]), "r"(a[3]), "r"(b[0]), "r"(b[1]));
}

// ---------------------------------------------------------------------------
// GEMM1: S[b,q,k] = sum_d (scale*Q[b,q,d]) * K[b,k,d]   (NT; scale folded in Q)
// Block 128x128, 8 warps 4(m)x2(n); warp tile 32x64 = 2x8 mma tiles. BK=8,
// double-buffered smem of float2{hi,lo}, one sync per k-tile,
// depth-2 register prefetch (LDG issued 2 iterations ahead of smem store).
// Grid: x = m-tile (never skipped), y = n-tile, so skipped tiles (n0 >= valid)
// form one contiguous instant-retire block per batch -> cleaner waves.
// ---------------------------------------------------------------------------
__global__ __launch_bounds__(256)
void qk_kernel(const float* __restrict__ Qm, const float* __restrict__ Km,
               const int* __restrict__ vl, float* __restrict__ Sarg)
{
    float* S = sel_or_scratch(Sarg);
    const int b = blockIdx.z;
    const int valid = vl[b];
    const int n0 = blockIdx.y * BN;
    if (n0 >= valid) return;                 // fully-masked tile: skip
    const int m0 = blockIdx.x * BM;

    const float* Qb = Qm + ((size_t)b * NQ + m0) * ND;
    const float* Kb = Km + ((size_t)b * NK + n0) * ND;

    __shared__ float2 A_s[2][BKc][AP];   // [k][m] = {hi,lo}
    __shared__ float2 B_s[2][BKc][AP];   // [k][n] = {hi,lo}

    const int tid  = threadIdx.x;
    const int lane = tid & 31;
    const int warp = tid >> 5;
    const int g    = lane >> 2;          // 0..7
    const int t    = lane & 3;           // 0..3
    const int wm   = (warp >> 1) * 32;
    const int wn   = (warp & 1) * 64;

    const int lrow = tid >> 1;           // 0..127
    const int lc4  = (tid & 1) * 4;      // 0 or 4

    const float* qptr = Qb + (size_t)lrow * ND + lc4;
    const float* kptr = Kb + (size_t)lrow * ND + lc4;

    const float scale = 0.04419417382415922f;  // 1/sqrt(512)
    const int NIT = ND / BKc;                  // 64

    float acc[2][8][4];
    #pragma unroll
    for (int i = 0; i < 2; i++)
        #pragma unroll
        for (int j = 0; j < 8; j++)
            #pragma unroll
            for (int r = 0; r < 4; r++) acc[i][j][r] = 0.0f;

    // prologue: tile 0 -> smem[0]; tile 1 -> register set P[1]
    float4 qP[2], kP[2];
    {
        float4 q0 = *reinterpret_cast<const float4*>(qptr);
        float4 k0 = *reinterpret_cast<const float4*>(kptr);
        #pragma unroll
        for (int j = 0; j < 4; j++) {
            A_s[0][lc4 + j][lrow] = split2(((const float*)&q0)[j] * scale);
            B_s[0][lc4 + j][lrow] = split2(((const float*)&k0)[j]);
        }
    }
    qP[1] = *reinterpret_cast<const float4*>(qptr + BKc);
    kP[1] = *reinterpret_cast<const float4*>(kptr + BKc);
    __syncthreads();

    int cur = 0;
    #pragma unroll 2
    for (int it = 0; it < NIT; it++) {
        // issue loads for it+2 into P[it&1] (~2 iterations of latency cover)
        if (it + 2 < NIT) {
            qP[it & 1] = *reinterpret_cast<const float4*>(qptr + (it + 2) * BKc);
            kP[it & 1] = *reinterpret_cast<const float4*>(kptr + (it + 2) * BKc);
        }
        uint32_t Ah[2][4], Al[2][4];
        #pragma unroll
        for (int i = 0; i < 2; i++) {
            const int mb = wm + i * 16;
            float2 p0 = A_s[cur][t    ][mb + g    ];
            float2 p1 = A_s[cur][t    ][mb + g + 8];
            float2 p2 = A_s[cur][t + 4][mb + g    ];
            float2 p3 = A_s[cur][t + 4][mb + g + 8];
            Ah[i][0] = __float_as_uint(p0.x); Al[i][0] = __float_as_uint(p0.y);
            Ah[i][1] = __float_as_uint(p1.x); Al[i][1] = __float_as_uint(p1.y);
            Ah[i][2] = __float_as_uint(p2.x); Al[i][2] = __float_as_uint(p2.y);
            Ah[i][3] = __float_as_uint(p3.x); Al[i][3] = __float_as_uint(p3.y);
        }
        #pragma unroll
        for (int j = 0; j < 8; j++) {
            const int nb = wn + j * 8;
            float2 q0 = B_s[cur][t    ][nb + g];
            float2 q1 = B_s[cur][t + 4][nb + g];
            uint32_t Bh[2] = { __float_as_uint(q0.x), __float_as_uint(q1.x) };
            uint32_t Bl[2] = { __float_as_uint(q0.y), __float_as_uint(q1.y) };
            #pragma unroll
            for (int i = 0; i < 2; i++) {
                mma_tf32(acc[i][j], Ah[i], Bh);
                mma_tf32(acc[i][j], Ah[i], Bl);
                mma_tf32(acc[i][j], Al[i], Bh);
            }
        }
        if (it + 1 < NIT) {
            const int nxt = cur ^ 1;
            const int s   = (it + 1) & 1;   // regs holding tile it+1
            #pragma unroll
            for (int j = 0; j < 4; j++) {
                A_s[nxt][lc4 + j][lrow] = split2(((const float*)&qP[s])[j] * scale);
                B_s[nxt][lc4 + j][lrow] = split2(((const float*)&kP[s])[j]);
            }
            __syncthreads();
            cur = nxt;
        }
    }

    #pragma unroll
    for (int i = 0; i < 2; i++) {
        #pragma unroll
        for (int j = 0; j < 8; j++) {
            const int rm = m0 + wm + i * 16 + g;
            const int cn = n0 + wn + j * 8 + 2 * t;
            float* p0 = S + ((size_t)b * NQ + rm) * NK + cn;
            *reinterpret_cast<float2*>(p0) = make_float2(acc[i][j][0], acc[i][j][1]);
            float* p1 = p0 + (size_t)8 * NK;
            *reinterpret_cast<float2*>(p1) = make_float2(acc[i][j][2], acc[i][j][3]);
        }
    }
}

// ---------------------------------------------------------------------------
// Masked softmax, in-place, one block per (b,q) row. NK = 2048 = 256 thr x 8.
// Fully register-resident. Chunk-predicated LOADS: chunks entirely beyond
// valid are never read (data there is unwritten scratch / masked junk and
// provably unused: max & exp passes predicate on k < valid, and masked e[i]
// are overwritten with 0 before the store pass). Boundary-chunk overreads hit
// qk-written scores (their tile has n0 < valid), so no NaN/poison exposure.
// zero_limit: stores cover [0, zero_limit); NK when W is a checked output,
// roundup(valid, BKc) when W is scratch (pv reads only below that bound).
// ---------------------------------------------------------------------------
__global__ __launch_bounds__(256)
void softmax_kernel(float* __restrict__ Warg, const int* __restrict__ vl,
                    int full_tail)
{
    float* W = sel_or_scratch(Warg);
    const int b = blockIdx.y;
    const int q = blockIdx.x;
    const int valid = vl[b];
    const int zero_limit = full_tail ? NK : ((valid + BKc - 1) & ~(BKc - 1));
    float* row = W + ((size_t)b * NQ + q) * NK;

    const int tid  = threadIdx.x;
    const int lane = tid & 31;
    const int wid  = tid >> 5;
    __shared__ float red[8];

    const int k0 = tid * 4;
    float4 v0 = make_float4(0.f, 0.f, 0.f, 0.f);
    float4 v1 = make_float4(0.f, 0.f, 0.f, 0.f);
    if (k0 < valid)        v0 = *reinterpret_cast<const float4*>(row + k0);
    if (k0 + 1024 < valid) v1 = *reinterpret_cast<const float4*>(row + k0 + 1024);
    float e[8] = { v0.x, v0.y, v0.z, v0.w, v1.x, v1.y, v1.z, v1.w };

    float m = -1e30f;
    #pragma unroll
    for (int i = 0; i < 8; i++) {
        const int k = (i < 4) ? (k0 + i) : (k0 + 1024 + i - 4);
        if (k < valid) m = fmaxf(m, e[i]);
    }
    #pragma unroll
    for (int off = 16; off > 0; off >>= 1)
        m = fmaxf(m, __shfl_xor_sync(0xFFFFFFFFu, m, off));
    if (lane == 0) red[wid] = m;
    __syncthreads();
    float mx = red[0];
    #pragma unroll
    for (int i = 1; i < 8; i++) mx = fmaxf(mx, red[i]);
    __syncthreads();    // red reused for the sum

    float s = 0.0f;
    #pragma unroll
    for (int i = 0; i < 8; i++) {
        const int k = (i < 4) ? (k0 + i) : (k0 + 1024 + i - 4);
        float ev = (k < valid) ? __expf(e[i] - mx) : 0.0f;
        e[i] = ev;
        s += ev;
    }
    #pragma unroll
    for (int off = 16; off > 0; off >>= 1)
        s += __shfl_xor_sync(0xFFFFFFFFu, s, off);
    if (lane == 0) red[wid] = s;
    __syncthreads();
    float tot = red[0];
    #pragma unroll
    for (int i = 1; i < 8; i++) tot += red[i];
    const float inv = 1.0f / tot;

    // stores: chunk-granular skip beyond zero_limit (16B-aligned chunks of 4)
    if (k0 < zero_limit) {
        v0 = make_float4(e[0] * inv, e[1] * inv, e[2] * inv, e[3] * inv);
        *reinterpret_cast<float4*>(row + k0) = v0;
    }
    if (k0 + 1024 < zero_limit) {
        v1 = make_float4(e[4] * inv, e[5] * inv, e[6] * inv, e[7] * inv);
        *reinterpret_cast<float4*>(row + k0 + 1024) = v1;
    }
}

// ---------------------------------------------------------------------------
// GEMM2: C[b,q,d] = sum_k W[b,q,k] * V[b,k,d]   (NN)
// K-loop truncated to roundup(valid,8): weights beyond valid are exact zeros.
// Depth-2 register prefetch: W streams from DRAM (first touch), 577-cyc
// latency needs ~2 iterations (~800 cyc) of cover.
// ---------------------------------------------------------------------------
__global__ __launch_bounds__(256)
void pv_kernel(const float* __restrict__ Warg, const float* __restrict__ Vm,
               const int* __restrict__ vl, float* __restrict__ Carg)
{
    const float* W = sel_or_scratch(const_cast<float*>(Warg));
    float* C = sel_or_scratch(Carg);
    const int b = blockIdx.z;
    const int valid = vl[b];
    const int n0 = blockIdx.x * BN;   // over D
    const int m0 = blockIdx.y * BM;   // over Q

    const float* Wb = W  + ((size_t)b * NQ + m0) * NK;
    const float* Vb = Vm + (size_t)b * NK * ND;

    __shared__ float2 A_s[2][BKc][AP];   // W: [k][m]
    __shared__ float2 B_s[2][BKc][AP];   // V: [k][n]

    const int tid  = threadIdx.x;
    const int lane = tid & 31;
    const int warp = tid >> 5;
    const int g    = lane >> 2;
    const int t    = lane & 3;
    const int wm   = (warp >> 1) * 32;
    const int wn   = (warp & 1) * 64;

    const int lrow = tid >> 1;           // W row 0..127
    const int lc4  = (tid & 1) * 4;      // k offset 0/4
    const int vrow = warp;               // V k-row 0..7

    const int kmax = min(NK, (valid + BKc - 1) & ~(BKc - 1));
    const int NIT  = kmax / BKc;         // >= 1

    float acc[2][8][4];
    #pragma unroll
    for (int i = 0; i < 2; i++)
        #pragma unroll
        for (int j = 0; j < 8; j++)
            #pragma unroll
            for (int r = 0; r < 4; r++) acc[i][j][r] = 0.0f;

    // prologue: tile 0 -> smem[0]; tile 1 -> register set P[1]
    float4 wP[2]; float vP[2][4];
    {
        float4 w0 = *reinterpret_cast<const float4*>(Wb + (size_t)lrow * NK + lc4);
        float v0[4];
        #pragma unroll
        for (int c = 0; c < 4; c++)
            v0[c] = Vb[(size_t)vrow * ND + n0 + c * 32 + lane];
        #pragma unroll
        for (int j = 0; j < 4; j++)
            A_s[0][lc4 + j][lrow] = split2(((const float*)&w0)[j]);
        #pragma unroll
        for (int c = 0; c < 4; c++)
            B_s[0][vrow][c * 32 + lane] = split2(v0[c]);
    }
    if (NIT > 1) {
        wP[1] = *reinterpret_cast<const float4*>(Wb + (size_t)lrow * NK + BKc + lc4);
        #pragma unroll
        for (int c = 0; c < 4; c++)
            vP[1][c] = Vb[(size_t)(BKc + vrow) * ND + n0 + c * 32 + lane];
    }
    __syncthreads();

    int cur = 0;
    #pragma unroll 2
    for (int it = 0; it < NIT; it++) {
        if (it + 2 < NIT) {
            const int s = it & 1;
            wP[s] = *reinterpret_cast<const float4*>(Wb + (size_t)lrow * NK + (it + 2) * BKc + lc4);
            #pragma unroll
            for (int c = 0; c < 4; c++)
                vP[s][c] = Vb[(size_t)((it + 2) * BKc + vrow) * ND + n0 + c * 32 + lane];
        }
        uint32_t Ah[2][4], Al[2][4];
        #pragma unroll
        for (int i = 0; i < 2; i++) {
            const int mb = wm + i * 16;
            float2 p0 = A_s[cur][t    ][mb + g    ];
            float2 p1 = A_s[cur][t    ][mb + g + 8];
            float2 p2 = A_s[cur][t + 4][mb + g    ];
            float2 p3 = A_s[cur][t + 4][mb + g + 8];
            Ah[i][0] = __float_as_uint(p0.x); Al[i][0] = __float_as_uint(p0.y);
            Ah[i][1] = __float_as_uint(p1.x); Al[i][1] = __float_as_uint(p1.y);
            Ah[i][2] = __float_as_uint(p2.x); Al[i][2] = __float_as_uint(p2.y);
            Ah[i][3] = __float_as_uint(p3.x); Al[i][3] = __float_as_uint(p3.y);
        }
        #pragma unroll
        for (int j = 0; j < 8; j++) {
            const int nb = wn + j * 8;
            float2 q0 = B_s[cur][t    ][nb + g];
            float2 q1 = B_s[cur][t + 4][nb + g];
            uint32_t Bh[2] = { __float_as_uint(q0.x), __float_as_uint(q1.x) };
            uint32_t Bl[2] = { __float_as_uint(q0.y), __float_as_uint(q1.y) };
            #pragma unroll
            for (int i = 0; i < 2; i++) {
                mma_tf32(acc[i][j], Ah[i], Bh);
                mma_tf32(acc[i][j], Ah[i], Bl);
                mma_tf32(acc[i][j], Al[i], Bh);
            }
        }
        if (it + 1 < NIT) {
            const int nxt = cur ^ 1;
            const int s   = (it + 1) & 1;   // regs holding tile it+1
            #pragma unroll
            for (int j = 0; j < 4; j++)
                A_s[nxt][lc4 + j][lrow] = split2(((const float*)&wP[s])[j]);
            #pragma unroll
            for (int c = 0; c < 4; c++)
                B_s[nxt][vrow][c * 32 + lane] = split2(vP[s][c]);
            __syncthreads();
            cur = nxt;
        }
    }

    #pragma unroll
    for (int i = 0; i < 2; i++) {
        #pragma unroll
        for (int j = 0; j < 8; j++) {
            const int rm = m0 + wm + i * 16 + g;
            const int cn = n0 + wn + j * 8 + 2 * t;
            float* p0 = C + ((size_t)b * NQ + rm) * ND + cn;
            *reinterpret_cast<float2*>(p0) = make_float2(acc[i][j][0], acc[i][j][1]);
            float* p1 = p0 + (size_t)8 * ND;
            *reinterpret_cast<float2*>(p1) = make_float2(acc[i][j][2], acc[i][j][3]);
        }
    }
}

// ---------------------------------------------------------------------------
// Launch. Output may be (context ++ weights), context only, or weights only;
// dispatch on out_size (unknown sizes fall back to the full layout).
// Dead work elided per case: pv skipped when context is unused; softmax tail
// stores skipped when weights live only in scratch; masked loads never issued.
// ---------------------------------------------------------------------------
extern "C" void kernel_launch(void* const* d_in, const int* in_sizes, int n_in,
                              void* d_out, int out_size)
{
    const float* Qp = (const float*)d_in[0];
    const float* Kp = (const float*)d_in[1];
    const float* Vp = (const float*)d_in[2];
    const int*   vl = (const int*)d_in[3];

    const long long BQD = (long long)NB * NQ * ND;   // 16,777,216
    const long long BQK = (long long)NB * NQ * NK;   // 67,108,864

    float* outp = (float*)d_out;
    float* ctx;
    float* wts;

    if ((long long)out_size == BQD) {                // context only
        ctx = outp;  wts = nullptr;
    } else if ((long long)out_size == BQK) {         // weights only
        wts = outp;  ctx = nullptr;
    } else {                                         // (context, weights) flattened
        ctx = outp;  wts = outp + BQD;
    }

    const int full_tail = (wts != nullptr);          // W checked => full zero tail

    dim3 blk(256);
    qk_kernel     <<<dim3(NQ / BM, NK / BN, NB), blk>>>(Qp, Kp, vl, wts);
    softmax_kernel<<<dim3(NQ, NB),               blk>>>(wts, vl, full_tail);
    if (ctx != nullptr)                              // context unused => pv is dead work
        pv_kernel <<<dim3(ND / BN, NQ / BM, NB), blk>>>(wts, Vp, vl, ctx);
}

// round 15
// speedup vs baseline: 1.1763x; 1.1763x over previous
#include <cuda_runtime.h>
#include <cstdint>

// Problem constants: B=16, Q=2048, K=2048, D=512, fp32.
#define NB 16
#define NQ 2048
#define NK 2048
#define ND 512

// Scratch for whichever of (context, weights) is NOT part of d_out.
__device__ float g_scratch[(size_t)NB * NQ * NK];
__device__ __forceinline__ float* sel_or_scratch(float* p) { return p ? p : g_scratch; }

#define BM 128
#define BN 128
#define BKc 8
#define AP 132   // float2 row pad: 2*132 mod 32 = 8 -> frag LDS.64 conflict-free

__device__ __forceinline__ float f2tf(float v) {
    uint32_t r; asm("cvt.rna.tf32.f32 %0, %1;" : "=r"(r) : "f"(v));
    return __uint_as_float(r);
}
// v = hi + lo, both tf32-representable. 3-term product residual ~(2^-11)^2.
__device__ __forceinline__ float2 split2(float v) {
    float hi = f2tf(v);
    return make_float2(hi, f2tf(v - hi));
}

// D += A*B, tf32 m16n8k8, A row-major, B col-major.
__device__ __forceinline__ void mma_tf32(float c[4], const uint32_t a[4], const uint32_t b[2]) {
    asm("mma.sync.aligned.m16n8k8.row.col.f32.tf32.tf32.f32 "
        "{%0,%1,%2,%3}, {%4,%5,%6,%7}, {%8,%9}, {%0,%1,%2,%3};"
        : "+f"(c[0]), "+f"(c[1]), "+f"(c[2]), "+f"(c[3])
        : "r"(a[0]), "r"(a[1]), "r"(a[2]), "r"(a[3]), "r"(b[0]), "r"(b[1]));
}

// ---------------------------------------------------------------------------
// GEMM1: S[b,q,k] = sum_d (scale*Q[b,q,d]) * K[b,k,d]   (NT; scale folded in Q)
// Block 128x128, 8 warps 4(m)x2(n); warp tile 32x64 = 2x8 mma tiles. BK=8,
// double-buffered smem of float2{hi,lo}, one sync per k-tile, depth-1
// register prefetch. __launch_bounds__(256,2): R13 ncu showed 132 regs ->
// 1 CTA/SM (occ 12.5%, tensor 38%); cap at 128 regs for 2 CTAs/SM.
// DRAM was 2.8% busy, so depth-2 prefetch was wasted registers.
// ---------------------------------------------------------------------------
__global__ __launch_bounds__(256, 2)
void qk_kernel(const float* __restrict__ Qm, const float* __restrict__ Km,
               const int* __restrict__ vl, float* __restrict__ Sarg)
{
    float* S = sel_or_scratch(Sarg);
    const int b = blockIdx.z;
    const int valid = vl[b];
    const int n0 = blockIdx.y * BN;
    if (n0 >= valid) return;                 // fully-masked tile: skip
    const int m0 = blockIdx.x * BM;

    const float* Qb = Qm + ((size_t)b * NQ + m0) * ND;
    const float* Kb = Km + ((size_t)b * NK + n0) * ND;

    __shared__ float2 A_s[2][BKc][AP];   // [k][m] = {hi,lo}
    __shared__ float2 B_s[2][BKc][AP];   // [k][n] = {hi,lo}

    const int tid  = threadIdx.x;
    const int lane = tid & 31;
    const int warp = tid >> 5;
    const int g    = lane >> 2;          // 0..7
    const int t    = lane & 3;           // 0..3
    const int wm   = (warp >> 1) * 32;
    const int wn   = (warp & 1) * 64;

    const int lrow = tid >> 1;           // 0..127
    const int lc4  = (tid & 1) * 4;      // 0 or 4

    const float* qptr = Qb + (size_t)lrow * ND + lc4;
    const float* kptr = Kb + (size_t)lrow * ND + lc4;

    const float scale = 0.04419417382415922f;  // 1/sqrt(512)
    const int NIT = ND / BKc;                  // 64

    float acc[2][8][4];
    #pragma unroll
    for (int i = 0; i < 2; i++)
        #pragma unroll
        for (int j = 0; j < 8; j++)
            #pragma unroll
            for (int r = 0; r < 4; r++) acc[i][j][r] = 0.0f;

    // preload tile 0
    float4 qN = *reinterpret_cast<const float4*>(qptr);
    float4 kN = *reinterpret_cast<const float4*>(kptr);
    #pragma unroll
    for (int j = 0; j < 4; j++) {
        A_s[0][lc4 + j][lrow] = split2(((const float*)&qN)[j] * scale);
        B_s[0][lc4 + j][lrow] = split2(((const float*)&kN)[j]);
    }
    __syncthreads();

    int cur = 0;
    for (int it = 0; it < NIT; it++) {
        // issue next-tile loads BEFORE compute (hidden under 48 MMAs)
        if (it + 1 < NIT) {
            qN = *reinterpret_cast<const float4*>(qptr + (it + 1) * BKc);
            kN = *reinterpret_cast<const float4*>(kptr + (it + 1) * BKc);
        }
        uint32_t Ah[2][4], Al[2][4];
        #pragma unroll
        for (int i = 0; i < 2; i++) {
            const int mb = wm + i * 16;
            float2 p0 = A_s[cur][t    ][mb + g    ];
            float2 p1 = A_s[cur][t    ][mb + g + 8];
            float2 p2 = A_s[cur][t + 4][mb + g    ];
            float2 p3 = A_s[cur][t + 4][mb + g + 8];
            Ah[i][0] = __float_as_uint(p0.x); Al[i][0] = __float_as_uint(p0.y);
            Ah[i][1] = __float_as_uint(p1.x); Al[i][1] = __float_as_uint(p1.y);
            Ah[i][2] = __float_as_uint(p2.x); Al[i][2] = __float_as_uint(p2.y);
            Ah[i][3] = __float_as_uint(p3.x); Al[i][3] = __float_as_uint(p3.y);
        }
        #pragma unroll
        for (int j = 0; j < 8; j++) {
            const int nb = wn + j * 8;
            float2 q0 = B_s[cur][t    ][nb + g];
            float2 q1 = B_s[cur][t + 4][nb + g];
            uint32_t Bh[2] = { __float_as_uint(q0.x), __float_as_uint(q1.x) };
            uint32_t Bl[2] = { __float_as_uint(q0.y), __float_as_uint(q1.y) };
            #pragma unroll
            for (int i = 0; i < 2; i++) {
                mma_tf32(acc[i][j], Ah[i], Bh);
                mma_tf32(acc[i][j], Ah[i], Bl);
                mma_tf32(acc[i][j], Al[i], Bh);
            }
        }
        if (it + 1 < NIT) {
            const int nxt = cur ^ 1;     // last read in prev iter; safe to fill
            #pragma unroll
            for (int j = 0; j < 4; j++) {
                A_s[nxt][lc4 + j][lrow] = split2(((const float*)&qN)[j] * scale);
                B_s[nxt][lc4 + j][lrow] = split2(((const float*)&kN)[j]);
            }
            __syncthreads();
            cur = nxt;
        }
    }

    #pragma unroll
    for (int i = 0; i < 2; i++) {
        #pragma unroll
        for (int j = 0; j < 8; j++) {
            const int rm = m0 + wm + i * 16 + g;
            const int cn = n0 + wn + j * 8 + 2 * t;
            float* p0 = S + ((size_t)b * NQ + rm) * NK + cn;
            *reinterpret_cast<float2*>(p0) = make_float2(acc[i][j][0], acc[i][j][1]);
            float* p1 = p0 + (size_t)8 * NK;
            *reinterpret_cast<float2*>(p1) = make_float2(acc[i][j][2], acc[i][j][3]);
        }
    }
}

// ---------------------------------------------------------------------------
// Masked softmax, in-place, one block per (b,q) row. NK = 2048 = 256 thr x 8.
// Fully register-resident, chunk-predicated loads and stores (see R7/R8).
// ---------------------------------------------------------------------------
__global__ __launch_bounds__(256)
void softmax_kernel(float* __restrict__ Warg, const int* __restrict__ vl,
                    int full_tail)
{
    float* W = sel_or_scratch(Warg);
    const int b = blockIdx.y;
    const int q = blockIdx.x;
    const int valid = vl[b];
    const int zero_limit = full_tail ? NK : ((valid + BKc - 1) & ~(BKc - 1));
    float* row = W + ((size_t)b * NQ + q) * NK;

    const int tid  = threadIdx.x;
    const int lane = tid & 31;
    const int wid  = tid >> 5;
    __shared__ float red[8];

    const int k0 = tid * 4;
    float4 v0 = make_float4(0.f, 0.f, 0.f, 0.f);
    float4 v1 = make_float4(0.f, 0.f, 0.f, 0.f);
    if (k0 < valid)        v0 = *reinterpret_cast<const float4*>(row + k0);
    if (k0 + 1024 < valid) v1 = *reinterpret_cast<const float4*>(row + k0 + 1024);
    float e[8] = { v0.x, v0.y, v0.z, v0.w, v1.x, v1.y, v1.z, v1.w };

    float m = -1e30f;
    #pragma unroll
    for (int i = 0; i < 8; i++) {
        const int k = (i < 4) ? (k0 + i) : (k0 + 1024 + i - 4);
        if (k < valid) m = fmaxf(m, e[i]);
    }
    #pragma unroll
    for (int off = 16; off > 0; off >>= 1)
        m = fmaxf(m, __shfl_xor_sync(0xFFFFFFFFu, m, off));
    if (lane == 0) red[wid] = m;
    __syncthreads();
    float mx = red[0];
    #pragma unroll
    for (int i = 1; i < 8; i++) mx = fmaxf(mx, red[i]);
    __syncthreads();    // red reused for the sum

    float s = 0.0f;
    #pragma unroll
    for (int i = 0; i < 8; i++) {
        const int k = (i < 4) ? (k0 + i) : (k0 + 1024 + i - 4);
        float ev = (k < valid) ? __expf(e[i] - mx) : 0.0f;
        e[i] = ev;
        s += ev;
    }
    #pragma unroll
    for (int off = 16; off > 0; off >>= 1)
        s += __shfl_xor_sync(0xFFFFFFFFu, s, off);
    if (lane == 0) red[wid] = s;
    __syncthreads();
    float tot = red[0];
    #pragma unroll
    for (int i = 1; i < 8; i++) tot += red[i];
    const float inv = 1.0f / tot;

    if (k0 < zero_limit) {
        v0 = make_float4(e[0] * inv, e[1] * inv, e[2] * inv, e[3] * inv);
        *reinterpret_cast<float4*>(row + k0) = v0;
    }
    if (k0 + 1024 < zero_limit) {
        v1 = make_float4(e[4] * inv, e[5] * inv, e[6] * inv, e[7] * inv);
        *reinterpret_cast<float4*>(row + k0 + 1024) = v1;
    }
}

// ---------------------------------------------------------------------------
// GEMM2: C[b,q,d] = sum_k W[b,q,k] * V[b,k,d]   (NN)
// K-loop truncated to roundup(valid,8). Depth-1 register prefetch +
// __launch_bounds__(256,2) for 2 CTAs/SM (same occupancy fix as qk).
// ---------------------------------------------------------------------------
__global__ __launch_bounds__(256, 2)
void pv_kernel(const float* __restrict__ Warg, const float* __restrict__ Vm,
               const int* __restrict__ vl, float* __restrict__ Carg)
{
    const float* W = sel_or_scratch(const_cast<float*>(Warg));
    float* C = sel_or_scratch(Carg);
    const int b = blockIdx.z;
    const int valid = vl[b];
    const int n0 = blockIdx.x * BN;   // over D
    const int m0 = blockIdx.y * BM;   // over Q

    const float* Wb = W  + ((size_t)b * NQ + m0) * NK;
    const float* Vb = Vm + (size_t)b * NK * ND;

    __shared__ float2 A_s[2][BKc][AP];   // W: [k][m]
    __shared__ float2 B_s[2][BKc][AP];   // V: [k][n]

    const int tid  = threadIdx.x;
    const int lane = tid & 31;
    const int warp = tid >> 5;
    const int g    = lane >> 2;
    const int t    = lane & 3;
    const int wm   = (warp >> 1) * 32;
    const int wn   = (warp & 1) * 64;

    const int lrow = tid >> 1;           // W row 0..127
    const int lc4  = (tid & 1) * 4;      // k offset 0/4
    const int vrow = warp;               // V k-row 0..7

    const int kmax = min(NK, (valid + BKc - 1) & ~(BKc - 1));
    const int NIT  = kmax / BKc;         // >= 1

    float acc[2][8][4];
    #pragma unroll
    for (int i = 0; i < 2; i++)
        #pragma unroll
        for (int j = 0; j < 8; j++)
            #pragma unroll
            for (int r = 0; r < 4; r++) acc[i][j][r] = 0.0f;

    // preload tile 0 (kmax >= 8 since valid >= 1)
    float4 wN = *reinterpret_cast<const float4*>(Wb + (size_t)lrow * NK + lc4);
    float vN[4];
    #pragma unroll
    for (int c = 0; c < 4; c++)
        vN[c] = Vb[(size_t)vrow * ND + n0 + c * 32 + lane];
    #pragma unroll
    for (int j = 0; j < 4; j++)
        A_s[0][lc4 + j][lrow] = split2(((const float*)&wN)[j]);
    #pragma unroll
    for (int c = 0; c < 4; c++)
        B_s[0][vrow][c * 32 + lane] = split2(vN[c]);
    __syncthreads();

    int cur = 0;
    for (int it = 0; it < NIT; it++) {
        if (it + 1 < NIT) {
            wN = *reinterpret_cast<const float4*>(Wb + (size_t)lrow * NK + (it + 1) * BKc + lc4);
            #pragma unroll
            for (int c = 0; c < 4; c++)
                vN[c] = Vb[(size_t)((it + 1) * BKc + vrow) * ND + n0 + c * 32 + lane];
        }
        uint32_t Ah[2][4], Al[2][4];
        #pragma unroll
        for (int i = 0; i < 2; i++) {
            const int mb = wm + i * 16;
            float2 p0 = A_s[cur][t    ][mb + g    ];
            float2 p1 = A_s[cur][t    ][mb + g + 8];
            float2 p2 = A_s[cur][t + 4][mb + g    ];
            float2 p3 = A_s[cur][t + 4][mb + g + 8];
            Ah[i][0] = __float_as_uint(p0.x); Al[i][0] = __float_as_uint(p0.y);
            Ah[i][1] = __float_as_uint(p1.x); Al[i][1] = __float_as_uint(p1.y);
            Ah[i][2] = __float_as_uint(p2.x); Al[i][2] = __float_as_uint(p2.y);
            Ah[i][3] = __float_as_uint(p3.x); Al[i][3] = __float_as_uint(p3.y);
        }
        #pragma unroll
        for (int j = 0; j < 8; j++) {
            const int nb = wn + j * 8;
            float2 q0 = B_s[cur][t    ][nb + g];
            float2 q1 = B_s[cur][t + 4][nb + g];
            uint32_t Bh[2] = { __float_as_uint(q0.x), __float_as_uint(q1.x) };
            uint32_t Bl[2] = { __float_as_uint(q0.y), __float_as_uint(q1.y) };
            #pragma unroll
            for (int i = 0; i < 2; i++) {
                mma_tf32(acc[i][j], Ah[i], Bh);
                mma_tf32(acc[i][j], Ah[i], Bl);
                mma_tf32(acc[i][j], Al[i], Bh);
            }
        }
        if (it + 1 < NIT) {
            const int nxt = cur ^ 1;
            #pragma unroll
            for (int j = 0; j < 4; j++)
                A_s[nxt][lc4 + j][lrow] = split2(((const float*)&wN)[j]);
            #pragma unroll
            for (int c = 0; c < 4; c++)
                B_s[nxt][vrow][c * 32 + lane] = split2(vN[c]);
            __syncthreads();
            cur = nxt;
        }
    }

    #pragma unroll
    for (int i = 0; i < 2; i++) {
        #pragma unroll
        for (int j = 0; j < 8; j++) {
            const int rm = m0 + wm + i * 16 + g;
            const int cn = n0 + wn + j * 8 + 2 * t;
            float* p0 = C + ((size_t)b * NQ + rm) * ND + cn;
            *reinterpret_cast<float2*>(p0) = make_float2(acc[i][j][0], acc[i][j][1]);
            float* p1 = p0 + (size_t)8 * ND;
            *reinterpret_cast<float2*>(p1) = make_float2(acc[i][j][2], acc[i][j][3]);
        }
    }
}

// ---------------------------------------------------------------------------
// Launch. Output may be (context ++ weights), context only, or weights only;
// dispatch on out_size (unknown sizes fall back to the full layout).
// Dead work elided per case: pv skipped when context is unused; softmax tail
// stores skipped when weights live only in scratch; masked loads never issued.
// ---------------------------------------------------------------------------
extern "C" void kernel_launch(void* const* d_in, const int* in_sizes, int n_in,
                              void* d_out, int out_size)
{
    const float* Qp = (const float*)d_in[0];
    const float* Kp = (const float*)d_in[1];
    const float* Vp = (const float*)d_in[2];
    const int*   vl = (const int*)d_in[3];

    const long long BQD = (long long)NB * NQ * ND;   // 16,777,216
    const long long BQK = (long long)NB * NQ * NK;   // 67,108,864

    float* outp = (float*)d_out;
    float* ctx;
    float* wts;

    if ((long long)out_size == BQD) {                // context only
        ctx = outp;  wts = nullptr;
    } else if ((long long)out_size == BQK) {         // weights only
        wts = outp;  ctx = nullptr;
    } else {                                         // (context, weights) flattened
        ctx = outp;  wts = outp + BQD;
    }

    const int full_tail = (wts != nullptr);          // W checked => full zero tail

    dim3 blk(256);
    qk_kernel     <<<dim3(NQ / BM, NK / BN, NB), blk>>>(Qp, Kp, vl, wts);
    softmax_kernel<<<dim3(NQ, NB),               blk>>>(wts, vl, full_tail);
    if (ctx != nullptr)                              // context unused => pv is dead work
        pv_kernel <<<dim3(ND / BN, NQ / BM, NB), blk>>>(wts, Vp, vl, ctx);
}